// round 8
// baseline (speedup 1.0000x reference)
#include <cuda_runtime.h>
#include <math.h>

// ---------------------------------------------------------------------------
// Fully-fused KAN generator, one block per batch sample (512 blocks x 256 thr).
// R8: phase-C math uses Blackwell packed fp32 (PTX fma.rn.f32x2 -> SASS FFMA2,
// 2 FMAs per fma-pipe slot, exact rn rounding).
//  - stages 1-3 (1 px/thread, COUT=4): accumulators packed over channel pairs;
//    the float4 weight IS two natural f32x2 pairs (no layout change); the
//    scalar feature is duplicated with one mov.b64.
//  - stage 4 (4 px/thread, COUT=3): accumulators packed over PIXEL pairs; the
//    feature pair is reused across all 3 channels; weights stored per-channel
//    DUPLICATED as f32x2 in SMEM.
// Features in HALOED arrays (border ring = spline(0) feats): no bounds checks.
// ---------------------------------------------------------------------------

#define F0A make_float4(0.0f, 0.125f, 0.75f, 0.125f)
#define F0B make_float2(0.0f, 0.0f)

typedef unsigned long long ull;

__device__ __forceinline__ ull pack2(float lo, float hi) {
    ull r;
    asm("mov.b64 %0, {%1, %2};" : "=l"(r) : "f"(lo), "f"(hi));
    return r;
}
__device__ __forceinline__ float2 unpack2(ull v) {
    float lo, hi;
    asm("mov.b64 {%0, %1}, %2;" : "=f"(lo), "=f"(hi) : "l"(v));
    return make_float2(lo, hi);
}
__device__ __forceinline__ void fma2(ull& acc, ull a, ull b) {
    asm("fma.rn.f32x2 %0, %1, %2, %0;" : "+l"(acc) : "l"(a), "l"(b));
}

__device__ __forceinline__ void spline_feats(float v, float4& fa, float2& fb) {
    const float H = 2.0f / 3.0f;
    float g[8];
#pragma unroll
    for (int i = 0; i < 8; i++) g[i] = (float)(i - 2) * H - 1.0f;
    float b0[7];
#pragma unroll
    for (int i = 0; i < 7; i++)
        b0[i] = (v >= g[i] && v < g[i + 1]) ? 1.0f : 0.0f;
    float b1[6];
#pragma unroll
    for (int i = 0; i < 6; i++)
        b1[i] = (v - g[i]) * (1.0f / (g[i + 1] - g[i])) * b0[i]
              + (g[i + 2] - v) * (1.0f / (g[i + 2] - g[i + 1])) * b0[i + 1];
    float b2[5];
#pragma unroll
    for (int i = 0; i < 5; i++)
        b2[i] = (v - g[i]) * (1.0f / (g[i + 2] - g[i])) * b1[i]
              + (g[i + 3] - v) * (1.0f / (g[i + 3] - g[i + 1])) * b1[i + 1];
    fa = make_float4(b2[0], b2[1], b2[2], b2[3]);
    fb = make_float2(b2[4], fmaxf(v, 0.0f));
}

__device__ __forceinline__ float fget(int f, const float4& fa, const float2& fb) {
    return (f == 0) ? fa.x : (f == 1) ? fa.y : (f == 2) ? fa.z
         : (f == 3) ? fa.w : (f == 4) ? fb.x : fb.y;
}

// ----------------------------- one conv stage ------------------------------
template <int HIN, int COUT, bool FINAL>
__device__ __forceinline__ void do_stage(
    const float* __restrict__ bw, const float* __restrict__ sw,
    float* act, float4* featA, float2* featB,
    ull* wshD, float* gout)
{
    constexpr int S2   = HIN * HIN;
    constexpr int NSRC = 4 * S2;
    constexpr int HOUT = 2 * HIN;
    constexpr int HP   = HIN + 2;
    constexpr int S2P  = HP * HP;
    constexpr bool PAIR = (S2 > 64);               // stage 4 only
    constexpr int NPX  = PAIR ? S2 / 64 : 1;       // 4 or 1
    constexpr int JSTR = (HIN >= 8) ? 64 / HIN : 1;
    const int tid = threadIdx.x;
    float* wshF = reinterpret_cast<float*>(wshD);

    // --- build combined weights: W[p][pos][c][wf][co], wf: 0-4 spline, 5 relu
    // PAIR: duplicated f32x2 per slot (ull); else plain float.
#pragma unroll
    for (int k = 0; k < 6; k++) {
        int e   = tid + k * 256;
        int co  = e & 3;
        int wf  = (e >> 2) % 6;
        int c   = (e / 24) & 3;
        int pos = (e / 96) & 3;
        int p   = e / 384;
        int py = p >> 1, px = p & 1;
        int ry = pos >> 1, rx = pos & 1;
        float s = 0.0f;
        if (co < COUT) {
            int ky0 = ry * (1 + py), nky = 1 + (ry ^ py);
            int kx0 = rx * (1 + px), nkx = 1 + (rx ^ px);
            for (int a = 0; a < nky; a++)
                for (int bb = 0; bb < nkx; bb++) {
                    int j = c * 9 + (ky0 + a) * 3 + (kx0 + bb);
                    s += (wf == 5) ? bw[co * 36 + j]
                                   : sw[(co * 36 + j) * 5 + wf];
                }
        }
        if (PAIR) wshD[e] = pack2(s, s);
        else      wshF[e] = s;
    }

    // --- border ring: spline(0) features (zero-padding contribution)
    {
        constexpr int NB = 2 * HP + 2 * HIN;
        for (int e = tid; e < 4 * NB; e += 256) {
            int c = e / NB, r = e % NB;
            int y, x;
            if (r < 2 * HP) { y = (r < HP) ? 0 : HP - 1; x = (r < HP) ? r : r - HP; }
            else { int r2 = r - 2 * HP;
                   y = 1 + ((r2 < HIN) ? r2 : r2 - HIN);
                   x = (r2 < HIN) ? 0 : HP - 1; }
            int slot = c * S2P + y * HP + x;
            featA[slot] = F0A;
            featB[slot] = F0B;
        }
    }

    // --- featurize interior source values (reads act)
#pragma unroll
    for (int k = 0; k < (NSRC + 255) / 256; k++) {
        int lv = tid + k * 256;
        if (NSRC >= 256 || lv < NSRC) {
            int c = lv / S2, rem = lv % S2;
            int y = rem / HIN, x = rem % HIN;
            float4 fa; float2 fb;
            spline_feats(act[lv], fa, fb);
            int slot = c * S2P + (y + 1) * HP + (x + 1);
            featA[slot] = fa;
            featB[slot] = fb;
        }
    }
    __syncthreads();

    // --- phase C
    const int p  = tid >> 6;      // warp-uniform parity
    const int l  = tid & 63;
    const int py = p >> 1, px = p & 1;

    if (S2 >= 64 || l < S2) {
        const int Yb = l / HIN;
        const int X  = l % HIN;
        const int base = (Yb + py) * HP + X + px;

        if (!PAIR) {
            // ---- 1 px/thread, COUT=4: acc packed over channel pairs
            ull acc01 = 0ull, acc23 = 0ull;
#pragma unroll
            for (int pos = 0; pos < 4; pos++) {
                const int ry = pos >> 1, rx = pos & 1;
#pragma unroll
                for (int c = 0; c < 4; c++) {
                    const int off = base + c * S2P + ry * HP + rx;
                    float4 fa = featA[off];
                    float2 fb = featB[off];
                    const ulonglong2* w = reinterpret_cast<const ulonglong2*>(
                        wshF + (((p * 4 + pos) * 4 + c) * 6) * 4);
#pragma unroll
                    for (int f = 0; f < 6; f++) {
                        ulonglong2 wv = w[f];      // (w0,w1),(w2,w3) f32x2
                        float s = fget(f, fa, fb);
                        ull s2 = pack2(s, s);
                        fma2(acc01, s2, wv.x);
                        fma2(acc23, s2, wv.y);
                    }
                }
            }
            float2 a01 = unpack2(acc01), a23 = unpack2(acc23);
            int y = 2 * Yb + py, x = 2 * X + px;
            act[0 * HOUT * HOUT + y * HOUT + x] = a01.x;
            act[1 * HOUT * HOUT + y * HOUT + x] = a01.y;
            act[2 * HOUT * HOUT + y * HOUT + x] = a23.x;
            act[3 * HOUT * HOUT + y * HOUT + x] = a23.y;
        } else {
            // ---- 4 px/thread (rows Yb+4j), COUT=3: acc packed over px pairs
            ull accP[2][3];
#pragma unroll
            for (int q = 0; q < 2; q++)
#pragma unroll
                for (int co = 0; co < 3; co++) accP[q][co] = 0ull;

#pragma unroll
            for (int pos = 0; pos < 4; pos++) {
                const int ry = pos >> 1, rx = pos & 1;
#pragma unroll
                for (int c = 0; c < 4; c++) {
                    const int off = base + c * S2P + ry * HP + rx;
                    float4 fa[NPX];
                    float2 fb[NPX];
#pragma unroll
                    for (int j = 0; j < NPX; j++) {
                        fa[j] = featA[off + j * JSTR * HP];
                        fb[j] = featB[off + j * JSTR * HP];
                    }
                    const int wb = ((p * 4 + pos) * 4 + c) * 6;
                    const ulonglong2* w2 =
                        reinterpret_cast<const ulonglong2*>(wshD + wb * 4);
#pragma unroll
                    for (int f = 0; f < 6; f++) {
                        ulonglong2 w01 = w2[f * 2];        // (w0dup, w1dup)
                        ull        w2d = wshD[(wb + f) * 4 + 2];  // w2dup
#pragma unroll
                        for (int q = 0; q < 2; q++) {
                            float slo = fget(f, fa[2 * q],     fb[2 * q]);
                            float shi = fget(f, fa[2 * q + 1], fb[2 * q + 1]);
                            ull s2 = pack2(slo, shi);
                            fma2(accP[q][0], s2, w01.x);
                            fma2(accP[q][1], s2, w01.y);
                            fma2(accP[q][2], s2, w2d);
                        }
                    }
                }
            }

#pragma unroll
            for (int q = 0; q < 2; q++) {
                float2 v0 = unpack2(accP[q][0]);
                float2 v1 = unpack2(accP[q][1]);
                float2 v2 = unpack2(accP[q][2]);
#pragma unroll
                for (int h = 0; h < 2; h++) {
                    int j = 2 * q + h;
                    int y = 2 * (Yb + j * JSTR) + py, x = 2 * X + px;
                    float o0 = h ? v0.y : v0.x;
                    float o1 = h ? v1.y : v1.x;
                    float o2 = h ? v2.y : v2.x;
                    gout[0 * HOUT * HOUT + y * HOUT + x] = tanhf(o0);
                    gout[1 * HOUT * HOUT + y * HOUT + x] = tanhf(o1);
                    gout[2 * HOUT * HOUT + y * HOUT + x] = tanhf(o2);
                }
            }
        }
    }
    __syncthreads();
}

// ----------------------------- fused kernel --------------------------------
__global__ void __launch_bounds__(256, 4) fused_kan_kernel(
    const float* __restrict__ x,
    const float* __restrict__ lin_w,
    const float* __restrict__ lin_b,
    const float* __restrict__ bw1, const float* __restrict__ sw1,
    const float* __restrict__ bw2, const float* __restrict__ sw2,
    const float* __restrict__ bw3, const float* __restrict__ sw3,
    const float* __restrict__ bw4, const float* __restrict__ sw4,
    float* __restrict__ out)
{
    __shared__ float  act[1024];
    __shared__ float4 featA[4 * 18 * 18];
    __shared__ float2 featB[4 * 18 * 18];
    __shared__ ull    wshD[1536];    // stage4: dup'd f32x2; stages 1-3: floats

    const int tid = threadIdx.x;
    const int b   = blockIdx.x;

    // linear + relu
    if (tid < 64) {
        int j = tid >> 2, qp = tid & 3;
        const float* xr = x + b * 100 + qp * 25;
        const float* wr = lin_w + j * 100 + qp * 25;
        float acc = 0.0f;
#pragma unroll
        for (int i = 0; i < 25; i++) acc = fmaf(xr[i], wr[i], acc);
        acc += __shfl_xor_sync(0xffffffffu, acc, 1);
        acc += __shfl_xor_sync(0xffffffffu, acc, 2);
        if (qp == 0) act[j] = fmaxf(acc + lin_b[j], 0.0f);
    }
    __syncthreads();

    do_stage<2, 4, false>(bw1, sw1, act, featA, featB, wshD, nullptr);
    do_stage<4, 4, false>(bw2, sw2, act, featA, featB, wshD, nullptr);
    do_stage<8, 4, false>(bw3, sw3, act, featA, featB, wshD, nullptr);
    do_stage<16, 3, true>(bw4, sw4, act, featA, featB, wshD,
                          out + (size_t)b * 3 * 32 * 32);
}

// ---------------------------------------------------------------------------
extern "C" void kernel_launch(void* const* d_in, const int* in_sizes, int n_in,
                              void* d_out, int out_size) {
    const float* x     = (const float*)d_in[0];
    const float* lin_w = (const float*)d_in[1];
    const float* lin_b = (const float*)d_in[2];
    const float* bw1   = (const float*)d_in[3];
    const float* sw1   = (const float*)d_in[4];
    const float* bw2   = (const float*)d_in[5];
    const float* sw2   = (const float*)d_in[6];
    const float* bw3   = (const float*)d_in[7];
    const float* sw3   = (const float*)d_in[8];
    const float* bw4   = (const float*)d_in[9];
    const float* sw4   = (const float*)d_in[10];

    fused_kan_kernel<<<512, 256>>>(x, lin_w, lin_b,
                                   bw1, sw1, bw2, sw2, bw3, sw3, bw4, sw4,
                                   (float*)d_out);
}